// round 4
// baseline (speedup 1.0000x reference)
#include <cuda_runtime.h>

// Shapes are fixed by the problem: B=16, P=12, N=2048, H=64, E=16384, Q=P.
#define BB 16
#define PP 12
#define NN 2048
#define HH 64
#define NH (NN*HH)          // 131072
#define BPc (BB*PP)         // 192
#define EE 16384
#define EPSV 1e-5f

// -------- scratch in __device__ globals (no allocations allowed) ----------
__device__ float  g_y[BB*PP*NN*HH];      // ~100.7 MB intermediate after graph conv
__device__ float2 g_stats1[BPc];         // (mean, rstd) for LN1
__device__ float2 g_part1[BPc*4];
__device__ float2 g_part2[BPc*256];
__device__ float2 g_stats2[BPc];         // (mean, rstd) for LN2
__device__ int    g_deg[NN];
__device__ float  g_dinv[NN];
__device__ int    g_rowptr[NN+1];
__device__ int    g_cursor[NN];
__device__ int    g_bucket[EE];
__device__ int    g_srcS[EE];
__device__ float  g_normS[EE];
__device__ int    g_is64;

// -------- edge dtype detection (jax may emit int32 despite jnp.int64) -----
__global__ void k_detect(const void* __restrict__ ei) {
    // First 32 int64 interpretations: if the buffer is really int32 pairs,
    // the high word is a dst/src value (almost surely nonzero) -> huge int64.
    long long v = ((const long long*)ei)[threadIdx.x];
    int ok = (v >= 0 && v < (long long)NN);
    unsigned m = __ballot_sync(0xffffffffu, ok);
    if (threadIdx.x == 0) g_is64 = (m == 0xffffffffu) ? 1 : 0;
}

__device__ __forceinline__ int edge_val(const void* ei, int idx, int is64) {
    return is64 ? (int)((const long long*)ei)[idx] : ((const int*)ei)[idx];
}

// -------- CSR build -------------------------------------------------------
__global__ void k_zero() {
    int i = blockIdx.x * blockDim.x + threadIdx.x;
    if (i < NN) { g_deg[i] = 0; g_cursor[i] = 0; }
}

__global__ void k_count(const void* __restrict__ ei) {
    int e = blockIdx.x * blockDim.x + threadIdx.x;
    if (e >= EE) return;
    int d = edge_val(ei, EE + e, g_is64);
    atomicAdd(&g_deg[d], 1);
}

__global__ void k_scan() {   // 1 block, 1024 threads: exclusive scan of deg[2048]
    __shared__ int sh[1024];
    int t = threadIdx.x;
    int a = g_deg[2*t], b = g_deg[2*t+1];
    sh[t] = a + b;
    __syncthreads();
    for (int off = 1; off < 1024; off <<= 1) {
        int v = (t >= off) ? sh[t - off] : 0;
        __syncthreads();
        sh[t] += v;
        __syncthreads();
    }
    int excl = (t > 0) ? sh[t-1] : 0;
    g_rowptr[2*t]   = excl;
    g_rowptr[2*t+1] = excl + a;
    if (t == 1023) g_rowptr[NN] = sh[1023];
    g_dinv[2*t]   = (a > 0) ? rsqrtf((float)a) : 0.f;
    g_dinv[2*t+1] = (b > 0) ? rsqrtf((float)b) : 0.f;
}

__global__ void k_scatter(const void* __restrict__ ei) {
    int e = blockIdx.x * blockDim.x + threadIdx.x;
    if (e >= EE) return;
    int is64 = g_is64;
    int d = edge_val(ei, EE + e, is64);
    int pos = g_rowptr[d] + atomicAdd(&g_cursor[d], 1);
    g_bucket[pos] = e;
}

// Sort each node's bucket by edge id -> deterministic accumulation order,
// then precompute (src, norm) per sorted slot.
__global__ void k_sortfill(const void* __restrict__ ei) {
    int n = blockIdx.x * blockDim.x + threadIdx.x;
    if (n >= NN) return;
    int beg = g_rowptr[n], end = g_rowptr[n+1];
    for (int i = beg + 1; i < end; i++) {        // tiny buckets (avg 8)
        int key = g_bucket[i]; int j = i - 1;
        while (j >= beg && g_bucket[j] > key) { g_bucket[j+1] = g_bucket[j]; j--; }
        g_bucket[j+1] = key;
    }
    int is64 = g_is64;
    float dn = g_dinv[n];
    for (int i = beg; i < end; i++) {
        int e = g_bucket[i];
        int s = edge_val(ei, e, is64);
        g_srcS[i]  = s;
        g_normS[i] = g_dinv[s] * dn;
    }
}

// -------- LN1 stats -------------------------------------------------------
__global__ void k_stats1(const float4* __restrict__ x4) {
    int bp = blockIdx.y, ch = blockIdx.x, t = threadIdx.x;
    int base = bp * (NH/4) + ch * 8192;          // quarter slice = 8192 float4
    float s = 0.f, q = 0.f;
    #pragma unroll
    for (int i = 0; i < 32; i++) {
        float4 v = x4[base + i*256 + t];
        s += v.x + v.y + v.z + v.w;
        q += v.x*v.x + v.y*v.y + v.z*v.z + v.w*v.w;
    }
    __shared__ float ss[256], sq[256];
    ss[t] = s; sq[t] = q; __syncthreads();
    for (int off = 128; off > 0; off >>= 1) {
        if (t < off) { ss[t] += ss[t+off]; sq[t] += sq[t+off]; }
        __syncthreads();
    }
    if (t == 0) g_part1[bp*4 + ch] = make_float2(ss[0], sq[0]);
}

__global__ void k_stats1b() {
    int bp = threadIdx.x;
    if (bp >= BPc) return;
    float s = 0.f, q = 0.f;
    for (int i = 0; i < 4; i++) { float2 v = g_part1[bp*4+i]; s += v.x; q += v.y; }
    float mean = s / (float)NH;
    float var  = q / (float)NH - mean * mean;
    g_stats1[bp] = make_float2(mean, rsqrtf(var + EPSV));
}

// -------- fused LN1 + LightGCN gather-accumulate + LN2 partial stats ------
__global__ void k_conv(const float* __restrict__ x,
                       const float* __restrict__ gw,
                       const float* __restrict__ gb) {
    int bp   = blockIdx.y;
    int w    = threadIdx.x >> 5;
    int lane = threadIdx.x & 31;
    int n    = blockIdx.x * 8 + w;               // one warp per node
    float2 st = g_stats1[bp];
    float m = st.x, r = st.y;
    const float* xs = x + bp * NH;
    int beg = g_rowptr[n], end = g_rowptr[n+1];
    int h = lane * 2;
    float2 acc = make_float2(0.f, 0.f);
    for (int i = beg; i < end; i++) {
        int   s   = g_srcS[i];
        float nrm = g_normS[i];
        float2 xv  = *(const float2*)(xs + s*HH + h);
        float2 gwv = *(const float2*)(gw + s*HH + h);
        float2 gbv = *(const float2*)(gb + s*HH + h);
        float v0 = fmaf((xv.x - m) * r, gwv.x, gbv.x);
        float v1 = fmaf((xv.y - m) * r, gwv.y, gbv.y);
        acc.x = fmaf(nrm, v0, acc.x);
        acc.y = fmaf(nrm, v1, acc.y);
    }
    *(float2*)(g_y + bp*NH + n*HH + h) = acc;

    // LN2 partial stats: fixed-order warp + block reduction (deterministic)
    float s1 = acc.x + acc.y;
    float q1 = acc.x*acc.x + acc.y*acc.y;
    for (int off = 16; off > 0; off >>= 1) {
        s1 += __shfl_down_sync(0xffffffffu, s1, off);
        q1 += __shfl_down_sync(0xffffffffu, q1, off);
    }
    __shared__ float ssum[8], ssq[8];
    if (lane == 0) { ssum[w] = s1; ssq[w] = q1; }
    __syncthreads();
    if (threadIdx.x == 0) {
        float s = 0.f, q = 0.f;
        for (int i = 0; i < 8; i++) { s += ssum[i]; q += ssq[i]; }
        g_part2[bp*256 + blockIdx.x] = make_float2(s, q);
    }
}

__global__ void k_stats2() {
    int bp = blockIdx.x, t = threadIdx.x;
    float2 v = g_part2[bp*256 + t];
    __shared__ float ss[256], sq[256];
    ss[t] = v.x; sq[t] = v.y; __syncthreads();
    for (int off = 128; off > 0; off >>= 1) {
        if (t < off) { ss[t] += ss[t+off]; sq[t] += sq[t+off]; }
        __syncthreads();
    }
    if (t == 0) {
        float mean = ss[0] / (float)NH;
        float var  = sq[0] / (float)NH - mean * mean;
        g_stats2[bp] = make_float2(mean, rsqrtf(var + EPSV));
    }
}

// -------- fused LN2 + 1x1 conv over periods + bias ------------------------
__global__ void k_out(const float* __restrict__ tw,
                      const float* __restrict__ tb,
                      const float* __restrict__ cw,
                      const float* __restrict__ cb,
                      float* __restrict__ out) {
    __shared__ float  scw[144], srow[12], scb[12];
    __shared__ float2 sst[12];
    int t   = threadIdx.x;
    int gid = blockIdx.x * 256 + t;
    int b   = gid >> 16;                 // 65536 (n,h2) positions per batch
    if (t < 144)              scw[t]      = cw[t];
    if (t >= 144 && t < 156)  scb[t-144]  = cb[t-144];
    if (t >= 160 && t < 172)  sst[t-160]  = g_stats2[b*PP + (t-160)];
    __syncthreads();
    if (t < 12) {
        float s = 0.f;
        for (int p = 0; p < 12; p++) s += scw[t*12 + p];
        srow[t] = s;
    }
    __syncthreads();

    int h2 = gid & 31;
    int n  = (gid >> 5) & 2047;
    int h  = h2 * 2;

    float2 tv[12];
    #pragma unroll
    for (int p = 0; p < 12; p++) {
        float2 yv = *(const float2*)(g_y + ((b*PP + p)*NN + n)*HH + h);
        float2 st = sst[p];
        tv[p].x = (yv.x - st.x) * st.y;
        tv[p].y = (yv.y - st.x) * st.y;
    }
    float2 tw2 = *(const float2*)(tw + n*HH + h);
    float2 tb2 = *(const float2*)(tb + n*HH + h);

    #pragma unroll
    for (int q = 0; q < 12; q++) {
        float ax = 0.f, ay = 0.f;
        #pragma unroll
        for (int p = 0; p < 12; p++) {
            float c = scw[q*12 + p];
            ax = fmaf(c, tv[p].x, ax);
            ay = fmaf(c, tv[p].y, ay);
        }
        // out = tw * sum_p(c*t_p) + tb * rowsum[q] + cb[q]
        float ox = fmaf(tw2.x, ax, fmaf(tb2.x, srow[q], scb[q]));
        float oy = fmaf(tw2.y, ay, fmaf(tb2.y, srow[q], scb[q]));
        *(float2*)(out + ((b*PP + q)*NN + n)*HH + h) = make_float2(ox, oy);
    }
}

// --------------------------------------------------------------------------
extern "C" void kernel_launch(void* const* d_in, const int* in_sizes, int n_in,
                              void* d_out, int out_size) {
    const float* x  = (const float*)d_in[0];
    const void*  ei = d_in[1];
    const float* gw = (const float*)d_in[2];
    const float* gb = (const float*)d_in[3];
    const float* tw = (const float*)d_in[4];
    const float* tb = (const float*)d_in[5];
    const float* cw = (const float*)d_in[6];
    const float* cb = (const float*)d_in[7];
    float* out = (float*)d_out;

    k_detect  <<<1, 32>>>(ei);
    k_zero    <<<8, 256>>>();
    k_count   <<<64, 256>>>(ei);
    k_scan    <<<1, 1024>>>();
    k_scatter <<<64, 256>>>(ei);
    k_sortfill<<<8, 256>>>(ei);
    k_stats1  <<<dim3(4, BPc), 256>>>((const float4*)x);
    k_stats1b <<<1, 256>>>();
    k_conv    <<<dim3(NN/8, BPc), 256>>>(x, gw, gb);
    k_stats2  <<<BPc, 256>>>();
    k_out     <<<4096, 256>>>(tw, tb, cw, cb, out);
}

// round 6
// speedup vs baseline: 1.1913x; 1.1913x over previous
#include <cuda_runtime.h>
#include <cuda_fp16.h>

// Shapes fixed by the problem: B=16, P=12, N=2048, H=64, E=16384, Q=P.
#define BB 16
#define PP 12
#define NN 2048
#define HH 64
#define NH (NN*HH)          // 131072
#define BPc (BB*PP)         // 192
#define EE 16384
#define EPSV 1e-5f

// -------- scratch in __device__ globals (no allocations allowed) ----------
__device__ __half2 g_xgh[BB*PP*NH/2];   // fp16(x*gw), 50 MB
__device__ __half2 g_yh [BB*PP*NH/2];   // fp16 y (post graph-conv), 50 MB
__device__ float2  g_part1[BPc*4];
__device__ float2  g_part2[BPc*256];
__device__ float2  g_stats2[BPc];
__device__ int     g_rowptr[NN+1];
__device__ uint2   g_sn[EE];            // per sorted slot: (src, norm bits)
__device__ uint2   g_AB[NN*32];         // packed half2 A | half2 B per (node, h-pair lane)

// ---------------- CSR build: ONE single-block kernel ----------------------
__global__ void k_csr(const void* __restrict__ ei) {
    extern __shared__ char sraw[];
    int*   sdeg  = (int*)sraw;                  // NN
    int*   srp   = sdeg + NN;                   // NN+1
    int*   scur  = srp + NN + 1;                // NN
    float* sdinv = (float*)(scur + NN);         // NN
    int*   sbuck = (int*)(sdinv + NN);          // EE
    int*   sc    = sbuck + EE;                  // 1024
    __shared__ int s_is64;
    int t = threadIdx.x;

    // edge dtype detection (jax may emit int32 despite jnp.int64)
    if (t < 32) {
        long long v = ((const long long*)ei)[t];
        int ok = (v >= 0 && v < (long long)NN);
        unsigned m = __ballot_sync(0xffffffffu, ok);
        if (t == 0) s_is64 = (m == 0xffffffffu) ? 1 : 0;
    }
    for (int i = t; i < NN; i += 1024) { sdeg[i] = 0; scur[i] = 0; }
    __syncthreads();
    int is64 = s_is64;

    // count in-degrees (smem atomics)
    for (int e = t; e < EE; e += 1024) {
        int d = is64 ? (int)((const long long*)ei)[EE + e] : ((const int*)ei)[EE + e];
        atomicAdd(&sdeg[d], 1);
    }
    __syncthreads();

    // exclusive scan of deg[2048] with 1024 threads
    int a = sdeg[2*t], b = sdeg[2*t+1];
    sc[t] = a + b;
    __syncthreads();
    for (int off = 1; off < 1024; off <<= 1) {
        int v = (t >= off) ? sc[t - off] : 0;
        __syncthreads();
        sc[t] += v;
        __syncthreads();
    }
    int excl = t ? sc[t-1] : 0;
    srp[2*t]   = excl;        g_rowptr[2*t]   = excl;
    srp[2*t+1] = excl + a;    g_rowptr[2*t+1] = excl + a;
    if (t == 1023) { srp[NN] = sc[1023]; g_rowptr[NN] = sc[1023]; }
    sdinv[2*t]   = a ? rsqrtf((float)a) : 0.f;
    sdinv[2*t+1] = b ? rsqrtf((float)b) : 0.f;
    __syncthreads();

    // scatter edge ids into per-dst buckets
    for (int e = t; e < EE; e += 1024) {
        int d = is64 ? (int)((const long long*)ei)[EE + e] : ((const int*)ei)[EE + e];
        int pos = srp[d] + atomicAdd(&scur[d], 1);
        sbuck[pos] = e;
    }
    __syncthreads();

    // sort each bucket by edge id (deterministic accumulation order), fill (src, norm)
    for (int n = t; n < NN; n += 1024) {
        int beg = srp[n], end = srp[n+1];
        for (int i = beg + 1; i < end; i++) {
            int key = sbuck[i]; int j = i - 1;
            while (j >= beg && sbuck[j] > key) { sbuck[j+1] = sbuck[j]; j--; }
            sbuck[j+1] = key;
        }
        float dn = sdinv[n];
        for (int i = beg; i < end; i++) {
            int e = sbuck[i];
            int s = is64 ? (int)((const long long*)ei)[e] : ((const int*)ei)[e];
            g_sn[i] = make_uint2((unsigned)s, __float_as_uint(sdinv[s] * dn));
        }
    }
}
#define SMEM_CSR ((NN*4) + ((NN+1)*4) + (NN*4) + (NN*4) + (EE*4) + (1024*4))

// ---- A[dst,h]=Σnrm*gw[src,h], B[dst,h]=Σnrm*gb[src,h] (bp-independent) ---
__global__ void k_ab(const float* __restrict__ gw, const float* __restrict__ gb) {
    int w = threadIdx.x >> 5, l = threadIdx.x & 31;
    int n = blockIdx.x * 8 + w;
    int beg = g_rowptr[n], end = g_rowptr[n+1];
    float A0 = 0.f, A1 = 0.f, B0 = 0.f, B1 = 0.f;
    for (int i = beg; i < end; i++) {
        uint2 sn = g_sn[i];
        int s = (int)sn.x;
        float nrm = __uint_as_float(sn.y);
        float2 w2 = *(const float2*)(gw + s*HH + 2*l);
        float2 b2 = *(const float2*)(gb + s*HH + 2*l);
        A0 = fmaf(nrm, w2.x, A0); A1 = fmaf(nrm, w2.y, A1);
        B0 = fmaf(nrm, b2.x, B0); B1 = fmaf(nrm, b2.y, B1);
    }
    __half2 hA = __floats2half2_rn(A0, A1);
    __half2 hB = __floats2half2_rn(B0, B1);
    g_AB[n*32 + l] = make_uint2(*reinterpret_cast<unsigned*>(&hA),
                                *reinterpret_cast<unsigned*>(&hB));
}

// -------- LN1 stats + fp16(x*gw) conversion (single pass over x) ----------
__global__ void k_stats1(const float4* __restrict__ x4,
                         const float4* __restrict__ gw4) {
    int bp = blockIdx.y, ch = blockIdx.x, t = threadIdx.x;
    float s = 0.f, q = 0.f;
    uint2* xg4 = (uint2*)g_xgh;
    #pragma unroll
    for (int i = 0; i < 32; i++) {
        int loc = ch*8192 + i*256 + t;            // float4 index within slice
        int gidx = bp*(NH/4) + loc;
        float4 v = x4[gidx];
        s += v.x + v.y + v.z + v.w;
        q += v.x*v.x + v.y*v.y + v.z*v.z + v.w*v.w;
        float4 g = gw4[loc];
        __half2 h0 = __floats2half2_rn(v.x*g.x, v.y*g.y);
        __half2 h1 = __floats2half2_rn(v.z*g.z, v.w*g.w);
        xg4[gidx] = make_uint2(*reinterpret_cast<unsigned*>(&h0),
                               *reinterpret_cast<unsigned*>(&h1));
    }
    __shared__ float ss[256], sq[256];
    ss[t] = s; sq[t] = q; __syncthreads();
    for (int off = 128; off > 0; off >>= 1) {
        if (t < off) { ss[t] += ss[t+off]; sq[t] += sq[t+off]; }
        __syncthreads();
    }
    if (t == 0) g_part1[bp*4 + ch] = make_float2(ss[0], sq[0]);
}

// -------- fused gather-accumulate + LN1 affine + LN2 partial stats --------
__global__ void k_conv() {
    __shared__ float sm_m, sm_r;
    __shared__ float ssum[8], ssq[8];
    int bp = blockIdx.y;
    int t  = threadIdx.x;
    if (t == 0) {                                   // inline LN1 finalize
        float s = 0.f, q = 0.f;
        for (int i = 0; i < 4; i++) { float2 v = g_part1[bp*4+i]; s += v.x; q += v.y; }
        float mean = s / (float)NH;
        float var  = q / (float)NH - mean*mean;
        sm_m = mean; sm_r = rsqrtf(var + EPSV);
    }
    __syncthreads();
    float m = sm_m, r = sm_r;

    int w = t >> 5, l = t & 31;
    int n = blockIdx.x * 8 + w;                     // one warp per node
    int beg = g_rowptr[n], end = g_rowptr[n+1];
    const __half2* xs = g_xgh + bp*(NH/2);
    float a0 = 0.f, a1 = 0.f;
    for (int i = beg; i < end; i++) {
        uint2 sn = g_sn[i];                         // uniform 8B broadcast load
        float nrm = __uint_as_float(sn.y);
        float2 xv = __half22float2(xs[sn.x*32 + l]);
        a0 = fmaf(nrm, xv.x, a0);
        a1 = fmaf(nrm, xv.y, a1);
    }
    uint2 ab = g_AB[n*32 + l];
    float2 A  = __half22float2(*reinterpret_cast<__half2*>(&ab.x));
    float2 Bv = __half22float2(*reinterpret_cast<__half2*>(&ab.y));
    float mr = m * r;
    float y0 = fmaf(r, a0, fmaf(-mr, A.x, Bv.x));
    float y1 = fmaf(r, a1, fmaf(-mr, A.y, Bv.y));
    g_yh[bp*(NH/2) + n*32 + l] = __floats2half2_rn(y0, y1);

    // deterministic LN2 partial stats from fp32 y
    float s1 = y0 + y1;
    float q1 = y0*y0 + y1*y1;
    for (int off = 16; off > 0; off >>= 1) {
        s1 += __shfl_down_sync(0xffffffffu, s1, off);
        q1 += __shfl_down_sync(0xffffffffu, q1, off);
    }
    if (l == 0) { ssum[w] = s1; ssq[w] = q1; }
    __syncthreads();
    if (t == 0) {
        float s = 0.f, q = 0.f;
        for (int i = 0; i < 8; i++) { s += ssum[i]; q += ssq[i]; }
        g_part2[bp*256 + blockIdx.x] = make_float2(s, q);
    }
}

__global__ void k_stats2() {
    int bp = blockIdx.x, t = threadIdx.x;
    float2 v = g_part2[bp*256 + t];
    __shared__ float ss[256], sq[256];
    ss[t] = v.x; sq[t] = v.y; __syncthreads();
    for (int off = 128; off > 0; off >>= 1) {
        if (t < off) { ss[t] += ss[t+off]; sq[t] += sq[t+off]; }
        __syncthreads();
    }
    if (t == 0) {
        float mean = ss[0] / (float)NH;
        float var  = sq[0] / (float)NH - mean*mean;
        g_stats2[bp] = make_float2(mean, rsqrtf(var + EPSV));
    }
}

// -------- fused LN2 + 1x1 conv over periods + bias (float4 vectorized) ----
__global__ void k_out(const float4* __restrict__ tw4,
                      const float4* __restrict__ tb4,
                      const float*  __restrict__ cw,
                      const float*  __restrict__ cb,
                      float4* __restrict__ out4) {
    __shared__ float  scw[144], srow[12], scb[12];
    __shared__ float2 sst[12];
    int t   = threadIdx.x;
    int gid = blockIdx.x * 256 + t;         // 524288 total (16 b * 2048 n * 16 h4)
    int b   = gid >> 15;                    // 32768 positions per batch
    if (t < 144)             scw[t]       = cw[t];
    if (t >= 144 && t < 156) scb[t-144]   = cb[t-144];
    if (t >= 160 && t < 172) sst[t-160]   = g_stats2[b*PP + (t-160)];
    __syncthreads();
    if (t < 12) {
        float s = 0.f;
        for (int p = 0; p < 12; p++) s += scw[t*12 + p];
        srow[t] = s;
    }
    __syncthreads();

    int h4   = gid & 15;
    int n    = (gid >> 4) & 2047;
    int pos4 = n*16 + h4;                   // float4/uint2 index within a slice

    const uint2* y4 = (const uint2*)g_yh;
    float4 tv[12];
    #pragma unroll
    for (int p = 0; p < 12; p++) {
        uint2 u = y4[(b*PP + p)*(NH/4) + pos4];
        float2 f0 = __half22float2(*reinterpret_cast<__half2*>(&u.x));
        float2 f1 = __half22float2(*reinterpret_cast<__half2*>(&u.y));
        float2 st = sst[p];
        tv[p].x = (f0.x - st.x) * st.y;
        tv[p].y = (f0.y - st.x) * st.y;
        tv[p].z = (f1.x - st.x) * st.y;
        tv[p].w = (f1.y - st.x) * st.y;
    }
    float4 tw = tw4[pos4];
    float4 tb = tb4[pos4];

    #pragma unroll
    for (int q = 0; q < 12; q++) {
        float ax = 0.f, ay = 0.f, az = 0.f, aw = 0.f;
        #pragma unroll
        for (int p = 0; p < 12; p++) {
            float c = scw[q*12 + p];
            ax = fmaf(c, tv[p].x, ax);
            ay = fmaf(c, tv[p].y, ay);
            az = fmaf(c, tv[p].z, az);
            aw = fmaf(c, tv[p].w, aw);
        }
        float4 o;
        o.x = fmaf(tw.x, ax, fmaf(tb.x, srow[q], scb[q]));
        o.y = fmaf(tw.y, ay, fmaf(tb.y, srow[q], scb[q]));
        o.z = fmaf(tw.z, az, fmaf(tb.z, srow[q], scb[q]));
        o.w = fmaf(tw.w, aw, fmaf(tb.w, srow[q], scb[q]));
        out4[(b*PP + q)*(NH/4) + pos4] = o;
    }
}

// --------------------------------------------------------------------------
extern "C" void kernel_launch(void* const* d_in, const int* in_sizes, int n_in,
                              void* d_out, int out_size) {
    const float* x  = (const float*)d_in[0];
    const void*  ei = d_in[1];
    const float* gw = (const float*)d_in[2];
    const float* gb = (const float*)d_in[3];
    const float* tw = (const float*)d_in[4];
    const float* tb = (const float*)d_in[5];
    const float* cw = (const float*)d_in[6];
    const float* cb = (const float*)d_in[7];
    float4* out = (float4*)d_out;

    cudaFuncSetAttribute(k_csr, cudaFuncAttributeMaxDynamicSharedMemorySize, SMEM_CSR);

    k_csr    <<<1, 1024, SMEM_CSR>>>(ei);
    k_ab     <<<256, 256>>>(gw, gb);
    k_stats1 <<<dim3(4, BPc), 256>>>((const float4*)x, (const float4*)gw);
    k_conv   <<<dim3(NN/8, BPc), 256>>>();
    k_stats2 <<<BPc, 256>>>();
    k_out    <<<2048, 256>>>((const float4*)tw, (const float4*)tb, cw, cb, out);
}

// round 7
// speedup vs baseline: 1.6410x; 1.3775x over previous
#include <cuda_runtime.h>
#include <cuda_fp16.h>

// Shapes fixed by the problem: B=16, P=12, N=2048, H=64, E=16384, Q=P.
#define BB 16
#define PP 12
#define NN 2048
#define HH 64
#define NH (NN*HH)          // 131072
#define BPc (BB*PP)         // 192
#define EE 16384
#define EPSV 1e-5f

// -------- scratch in __device__ globals (no allocations allowed) ----------
__device__ __half2 g_xgh[BB*PP*NH/2];   // fp16(x*gw), 50 MB
__device__ __half2 g_yh [BB*PP*NH/2];   // fp16 y (post graph-conv), 50 MB
__device__ float2  g_part1[BPc*4];
__device__ float2  g_part2[BPc*256];
__device__ float2  g_stats2[BPc];
__device__ int     g_rowptr[NN+1];
__device__ uint2   g_sn[EE];            // per sorted slot: (src, norm bits)
__device__ uint2   g_AB[NN*32];         // packed half2 A | half2 B per (node, h-pair lane)

// ---------------- CSR build: ONE single-block kernel, smem-resident -------
// smem layout (bytes): sdst 64K | ssrc 64K | sbuck 64K | sdeg 8K | srp 8K+4 |
//                      sdinv 8K | swarp 128
#define SMEM_CSR (EE*4*3 + NN*4 + (NN+1)*4 + NN*4 + 128)
__global__ void k_csr(const void* __restrict__ ei) {
    extern __shared__ char sraw[];
    int*   sdst  = (int*)sraw;
    int*   ssrc  = sdst + EE;
    int*   sbuck = ssrc + EE;
    int*   sdeg  = sbuck + EE;        // doubles as scatter cursor later
    int*   srp   = sdeg + NN;
    float* sdinv = (float*)(srp + NN + 1);
    int*   swarp = (int*)(sdinv + NN);
    __shared__ int s_is64;
    int t = threadIdx.x, lane = t & 31, wid = t >> 5;

    // edge dtype detection (jax may emit int32 despite jnp.int64)
    if (t < 32) {
        long long v = ((const long long*)ei)[t];
        int ok = (v >= 0 && v < (long long)NN);
        unsigned m = __ballot_sync(0xffffffffu, ok);
        if (t == 0) s_is64 = (m == 0xffffffffu) ? 1 : 0;
    }
    for (int i = t; i < NN; i += 1024) sdeg[i] = 0;
    __syncthreads();
    int is64 = s_is64;

    // single streaming pass over edges: cache src/dst, count in-degrees
    for (int e = t; e < EE; e += 1024) {
        int s, d;
        if (is64) {
            s = (int)((const long long*)ei)[e];
            d = (int)((const long long*)ei)[EE + e];
        } else {
            s = ((const int*)ei)[e];
            d = ((const int*)ei)[EE + e];
        }
        ssrc[e] = s; sdst[e] = d;
        atomicAdd(&sdeg[d], 1);
    }
    __syncthreads();

    // exclusive scan of deg[2048] via warp shuffles (1024 thr, 2 vals each)
    int a  = sdeg[2*t], b2 = sdeg[2*t+1];
    int v  = a + b2;
    #pragma unroll
    for (int off = 1; off < 32; off <<= 1) {
        int u = __shfl_up_sync(0xffffffffu, v, off);
        if (lane >= off) v += u;
    }
    if (lane == 31) swarp[wid] = v;
    __syncthreads();
    if (wid == 0) {
        int u = swarp[lane];
        #pragma unroll
        for (int off = 1; off < 32; off <<= 1) {
            int x2 = __shfl_up_sync(0xffffffffu, u, off);
            if (lane >= off) u += x2;
        }
        swarp[lane] = u;
    }
    __syncthreads();
    int woff = wid ? swarp[wid-1] : 0;
    int incl = v + woff;
    int excl = incl - (a + b2);
    srp[2*t]   = excl;        g_rowptr[2*t]   = excl;
    srp[2*t+1] = excl + a;    g_rowptr[2*t+1] = excl + a;
    if (t == 1023) { srp[NN] = incl; g_rowptr[NN] = incl; }
    sdinv[2*t]   = a  ? rsqrtf((float)a)  : 0.f;
    sdinv[2*t+1] = b2 ? rsqrtf((float)b2) : 0.f;
    // reset sdeg for reuse as scatter cursor
    sdeg[2*t] = 0; sdeg[2*t+1] = 0;
    __syncthreads();

    // scatter edge ids into per-dst buckets (all smem)
    for (int e = t; e < EE; e += 1024) {
        int d = sdst[e];
        int pos = srp[d] + atomicAdd(&sdeg[d], 1);
        sbuck[pos] = e;
    }
    __syncthreads();

    // sort each bucket by edge id (deterministic accumulation), fill (src, norm)
    for (int n = t; n < NN; n += 1024) {
        int beg = srp[n], end = srp[n+1];
        for (int i = beg + 1; i < end; i++) {
            int key = sbuck[i]; int j = i - 1;
            while (j >= beg && sbuck[j] > key) { sbuck[j+1] = sbuck[j]; j--; }
            sbuck[j+1] = key;
        }
        float dn = sdinv[n];
        for (int i = beg; i < end; i++) {
            int s = ssrc[sbuck[i]];
            g_sn[i] = make_uint2((unsigned)s, __float_as_uint(sdinv[s] * dn));
        }
    }
}

// ---- A[dst,h]=Σnrm*gw[src,h], B[dst,h]=Σnrm*gb[src,h] (bp-independent) ---
__global__ void k_ab(const float* __restrict__ gw, const float* __restrict__ gb) {
    int w = threadIdx.x >> 5, l = threadIdx.x & 31;
    int n = blockIdx.x * 8 + w;
    int beg = g_rowptr[n], end = g_rowptr[n+1];
    float A0 = 0.f, A1 = 0.f, B0 = 0.f, B1 = 0.f;
    for (int i = beg; i < end; i++) {
        uint2 sn = g_sn[i];
        int s = (int)sn.x;
        float nrm = __uint_as_float(sn.y);
        float2 w2 = *(const float2*)(gw + s*HH + 2*l);
        float2 b2 = *(const float2*)(gb + s*HH + 2*l);
        A0 = fmaf(nrm, w2.x, A0); A1 = fmaf(nrm, w2.y, A1);
        B0 = fmaf(nrm, b2.x, B0); B1 = fmaf(nrm, b2.y, B1);
    }
    __half2 hA = __floats2half2_rn(A0, A1);
    __half2 hB = __floats2half2_rn(B0, B1);
    g_AB[n*32 + l] = make_uint2(*reinterpret_cast<unsigned*>(&hA),
                                *reinterpret_cast<unsigned*>(&hB));
}

// -------- LN1 stats + fp16(x*gw) conversion (single pass over x) ----------
__global__ void k_stats1(const float4* __restrict__ x4,
                         const float4* __restrict__ gw4) {
    int bp = blockIdx.y, ch = blockIdx.x, t = threadIdx.x;
    float s = 0.f, q = 0.f;
    uint2* xg4 = (uint2*)g_xgh;
    #pragma unroll
    for (int i = 0; i < 32; i++) {
        int loc = ch*8192 + i*256 + t;            // float4 index within slice
        int gidx = bp*(NH/4) + loc;
        float4 v = x4[gidx];
        s += v.x + v.y + v.z + v.w;
        q += v.x*v.x + v.y*v.y + v.z*v.z + v.w*v.w;
        float4 g = gw4[loc];
        __half2 h0 = __floats2half2_rn(v.x*g.x, v.y*g.y);
        __half2 h1 = __floats2half2_rn(v.z*g.z, v.w*g.w);
        xg4[gidx] = make_uint2(*reinterpret_cast<unsigned*>(&h0),
                               *reinterpret_cast<unsigned*>(&h1));
    }
    __shared__ float ss[256], sq[256];
    ss[t] = s; sq[t] = q; __syncthreads();
    for (int off = 128; off > 0; off >>= 1) {
        if (t < off) { ss[t] += ss[t+off]; sq[t] += sq[t+off]; }
        __syncthreads();
    }
    if (t == 0) g_part1[bp*4 + ch] = make_float2(ss[0], sq[0]);
}

// -- fused gather: one warp = one node, ALL 12 p of one batch b ------------
__global__ void k_conv() {
    __shared__ float2 sstats[PP];               // (mean, rstd) per p of this b
    __shared__ float  ssum[PP][8], ssq[PP][8];
    int b = blockIdx.y;
    int t = threadIdx.x;
    if (t < PP) {                               // inline LN1 finalize, one p each
        int bp = b*PP + t;
        float s = 0.f, q = 0.f;
        for (int i = 0; i < 4; i++) { float2 v = g_part1[bp*4+i]; s += v.x; q += v.y; }
        float mean = s / (float)NH;
        float var  = q / (float)NH - mean*mean;
        sstats[t] = make_float2(mean, rsqrtf(var + EPSV));
    }
    __syncthreads();

    int w = t >> 5, l = t & 31;
    int n = blockIdx.x * 8 + w;
    int beg = g_rowptr[n], end = g_rowptr[n+1];
    const __half2* base = g_xgh + b*PP*(NH/2) + l;

    float ax[PP], ay[PP];
    #pragma unroll
    for (int p = 0; p < PP; p++) { ax[p] = 0.f; ay[p] = 0.f; }

    uint2 sn = (beg < end) ? g_sn[beg] : make_uint2(0u, 0u);
    for (int i = beg; i < end; i++) {
        uint2 cur = sn;
        if (i + 1 < end) sn = g_sn[i+1];        // prefetch next index
        float nrm = __uint_as_float(cur.y);
        const __half2* src = base + cur.x * 32;
        #pragma unroll
        for (int p = 0; p < PP; p++) {          // 12 imm-offset loads, MLP=12
            float2 xv = __half22float2(src[p*(NH/2)]);
            ax[p] = fmaf(nrm, xv.x, ax[p]);
            ay[p] = fmaf(nrm, xv.y, ay[p]);
        }
    }

    uint2 ab = g_AB[n*32 + l];
    float2 A  = __half22float2(*reinterpret_cast<__half2*>(&ab.x));
    float2 Bv = __half22float2(*reinterpret_cast<__half2*>(&ab.y));

    #pragma unroll
    for (int p = 0; p < PP; p++) {
        float2 st = sstats[p];
        float mr = st.x * st.y;
        float y0 = fmaf(st.y, ax[p], fmaf(-mr, A.x, Bv.x));
        float y1 = fmaf(st.y, ay[p], fmaf(-mr, A.y, Bv.y));
        g_yh[(b*PP + p)*(NH/2) + n*32 + l] = __floats2half2_rn(y0, y1);
        float s1 = y0 + y1;
        float q1 = y0*y0 + y1*y1;
        #pragma unroll
        for (int off = 16; off > 0; off >>= 1) {
            s1 += __shfl_down_sync(0xffffffffu, s1, off);
            q1 += __shfl_down_sync(0xffffffffu, q1, off);
        }
        if (l == 0) { ssum[p][w] = s1; ssq[p][w] = q1; }
    }
    __syncthreads();
    if (t < PP) {
        float s = 0.f, q = 0.f;
        for (int i = 0; i < 8; i++) { s += ssum[t][i]; q += ssq[t][i]; }
        g_part2[(b*PP + t)*256 + blockIdx.x] = make_float2(s, q);
    }
}

__global__ void k_stats2() {
    int bp = blockIdx.x, t = threadIdx.x;
    float2 v = g_part2[bp*256 + t];
    __shared__ float ss[256], sq[256];
    ss[t] = v.x; sq[t] = v.y; __syncthreads();
    for (int off = 128; off > 0; off >>= 1) {
        if (t < off) { ss[t] += ss[t+off]; sq[t] += sq[t+off]; }
        __syncthreads();
    }
    if (t == 0) {
        float mean = ss[0] / (float)NH;
        float var  = sq[0] / (float)NH - mean*mean;
        g_stats2[bp] = make_float2(mean, rsqrtf(var + EPSV));
    }
}

// -------- fused LN2 + 1x1 conv over periods + bias (float4 vectorized) ----
__global__ void k_out(const float4* __restrict__ tw4,
                      const float4* __restrict__ tb4,
                      const float*  __restrict__ cw,
                      const float*  __restrict__ cb,
                      float4* __restrict__ out4) {
    __shared__ float  scw[144], srow[12], scb[12];
    __shared__ float2 sst[12];
    int t   = threadIdx.x;
    int gid = blockIdx.x * 256 + t;         // 524288 total (16 b * 2048 n * 16 h4)
    int b   = gid >> 15;                    // 32768 positions per batch
    if (t < 144)             scw[t]       = cw[t];
    if (t >= 144 && t < 156) scb[t-144]   = cb[t-144];
    if (t >= 160 && t < 172) sst[t-160]   = g_stats2[b*PP + (t-160)];
    __syncthreads();
    if (t < 12) {
        float s = 0.f;
        for (int p = 0; p < 12; p++) s += scw[t*12 + p];
        srow[t] = s;
    }
    __syncthreads();

    int h4   = gid & 15;
    int n    = (gid >> 4) & 2047;
    int pos4 = n*16 + h4;

    const uint2* y4 = (const uint2*)g_yh;
    float4 tv[12];
    #pragma unroll
    for (int p = 0; p < 12; p++) {
        uint2 u = y4[(b*PP + p)*(NH/4) + pos4];
        float2 f0 = __half22float2(*reinterpret_cast<__half2*>(&u.x));
        float2 f1 = __half22float2(*reinterpret_cast<__half2*>(&u.y));
        float2 st = sst[p];
        tv[p].x = (f0.x - st.x) * st.y;
        tv[p].y = (f0.y - st.x) * st.y;
        tv[p].z = (f1.x - st.x) * st.y;
        tv[p].w = (f1.y - st.x) * st.y;
    }
    float4 tw = tw4[pos4];
    float4 tb = tb4[pos4];

    #pragma unroll
    for (int q = 0; q < 12; q++) {
        float ax = 0.f, ay = 0.f, az = 0.f, aw = 0.f;
        #pragma unroll
        for (int p = 0; p < 12; p++) {
            float c = scw[q*12 + p];
            ax = fmaf(c, tv[p].x, ax);
            ay = fmaf(c, tv[p].y, ay);
            az = fmaf(c, tv[p].z, az);
            aw = fmaf(c, tv[p].w, aw);
        }
        float4 o;
        o.x = fmaf(tw.x, ax, fmaf(tb.x, srow[q], scb[q]));
        o.y = fmaf(tw.y, ay, fmaf(tb.y, srow[q], scb[q]));
        o.z = fmaf(tw.z, az, fmaf(tb.z, srow[q], scb[q]));
        o.w = fmaf(tw.w, aw, fmaf(tb.w, srow[q], scb[q]));
        out4[(b*PP + q)*(NH/4) + pos4] = o;
    }
}

// --------------------------------------------------------------------------
extern "C" void kernel_launch(void* const* d_in, const int* in_sizes, int n_in,
                              void* d_out, int out_size) {
    const float* x  = (const float*)d_in[0];
    const void*  ei = d_in[1];
    const float* gw = (const float*)d_in[2];
    const float* gb = (const float*)d_in[3];
    const float* tw = (const float*)d_in[4];
    const float* tb = (const float*)d_in[5];
    const float* cw = (const float*)d_in[6];
    const float* cb = (const float*)d_in[7];
    float4* out = (float4*)d_out;

    cudaFuncSetAttribute(k_csr, cudaFuncAttributeMaxDynamicSharedMemorySize, SMEM_CSR);

    k_csr    <<<1, 1024, SMEM_CSR>>>(ei);
    k_ab     <<<256, 256>>>(gw, gb);
    k_stats1 <<<dim3(4, BPc), 256>>>((const float4*)x, (const float4*)gw);
    k_conv   <<<dim3(NN/8, BB), 256>>>();
    k_stats2 <<<BPc, 256>>>();
    k_out    <<<2048, 256>>>((const float4*)tw, (const float4*)tb, cw, cb, out);
}

// round 8
// speedup vs baseline: 1.6911x; 1.0305x over previous
#include <cuda_runtime.h>
#include <cuda_fp16.h>

// Shapes fixed by the problem: B=16, P=12, N=2048, H=64, E=16384, Q=P.
#define BB 16
#define PP 12
#define NN 2048
#define HH 64
#define NH (NN*HH)          // 131072
#define BPc (BB*PP)         // 192
#define EE 16384
#define EPSV 1e-5f

// -------- scratch in __device__ globals (no allocations allowed) ----------
// g_xgh layout: [b][n][p][h] (fp16 x*gw) -> per-node row of 1536B contiguous
__device__ __half2 g_xgh[BB*NN*PP*HH/2];   // 50 MB
// g_yh layout: [b][p][n][h] (fp16 y)
__device__ __half2 g_yh [BB*PP*NN*HH/2];   // 50 MB
__device__ float2  g_part1[BPc*4];
__device__ float2  g_part2[BPc*256];
__device__ float2  g_stats2[BPc];
__device__ int     g_rowptr[NN+1];
__device__ uint2   g_sn[EE];            // per sorted slot: (src, norm bits)
__device__ uint2   g_AB[NN*32];         // packed half2 A | half2 B per (node, h-pair)

// ---------------- CSR build: ONE single-block kernel, smem-resident -------
#define SMEM_CSR (EE*4*3 + NN*4 + (NN+1)*4 + NN*4 + 128)
__global__ void k_csr(const void* __restrict__ ei) {
    extern __shared__ char sraw[];
    int*   sdst  = (int*)sraw;
    int*   ssrc  = sdst + EE;
    int*   sbuck = ssrc + EE;
    int*   sdeg  = sbuck + EE;        // doubles as scatter cursor later
    int*   srp   = sdeg + NN;
    float* sdinv = (float*)(srp + NN + 1);
    int*   swarp = (int*)(sdinv + NN);
    __shared__ int s_is64;
    int t = threadIdx.x, lane = t & 31, wid = t >> 5;

    // edge dtype detection (jax may emit int32 despite jnp.int64)
    if (t < 32) {
        long long v = ((const long long*)ei)[t];
        int ok = (v >= 0 && v < (long long)NN);
        unsigned m = __ballot_sync(0xffffffffu, ok);
        if (t == 0) s_is64 = (m == 0xffffffffu) ? 1 : 0;
    }
    for (int i = t; i < NN; i += 1024) sdeg[i] = 0;
    __syncthreads();
    int is64 = s_is64;

    for (int e = t; e < EE; e += 1024) {
        int s, d;
        if (is64) {
            s = (int)((const long long*)ei)[e];
            d = (int)((const long long*)ei)[EE + e];
        } else {
            s = ((const int*)ei)[e];
            d = ((const int*)ei)[EE + e];
        }
        ssrc[e] = s; sdst[e] = d;
        atomicAdd(&sdeg[d], 1);
    }
    __syncthreads();

    // exclusive scan of deg[2048] via warp shuffles
    int a  = sdeg[2*t], b2 = sdeg[2*t+1];
    int v  = a + b2;
    #pragma unroll
    for (int off = 1; off < 32; off <<= 1) {
        int u = __shfl_up_sync(0xffffffffu, v, off);
        if (lane >= off) v += u;
    }
    if (lane == 31) swarp[wid] = v;
    __syncthreads();
    if (wid == 0) {
        int u = swarp[lane];
        #pragma unroll
        for (int off = 1; off < 32; off <<= 1) {
            int x2 = __shfl_up_sync(0xffffffffu, u, off);
            if (lane >= off) u += x2;
        }
        swarp[lane] = u;
    }
    __syncthreads();
    int woff = wid ? swarp[wid-1] : 0;
    int incl = v + woff;
    int excl = incl - (a + b2);
    srp[2*t]   = excl;        g_rowptr[2*t]   = excl;
    srp[2*t+1] = excl + a;    g_rowptr[2*t+1] = excl + a;
    if (t == 1023) { srp[NN] = incl; g_rowptr[NN] = incl; }
    sdinv[2*t]   = a  ? rsqrtf((float)a)  : 0.f;
    sdinv[2*t+1] = b2 ? rsqrtf((float)b2) : 0.f;
    sdeg[2*t] = 0; sdeg[2*t+1] = 0;
    __syncthreads();

    for (int e = t; e < EE; e += 1024) {
        int d = sdst[e];
        int pos = srp[d] + atomicAdd(&sdeg[d], 1);
        sbuck[pos] = e;
    }
    __syncthreads();

    // sort each bucket by edge id (deterministic accumulation), fill (src, norm)
    for (int n = t; n < NN; n += 1024) {
        int beg = srp[n], end = srp[n+1];
        for (int i = beg + 1; i < end; i++) {
            int key = sbuck[i]; int j = i - 1;
            while (j >= beg && sbuck[j] > key) { sbuck[j+1] = sbuck[j]; j--; }
            sbuck[j+1] = key;
        }
        float dn = sdinv[n];
        for (int i = beg; i < end; i++) {
            int s = ssrc[sbuck[i]];
            g_sn[i] = make_uint2((unsigned)s, __float_as_uint(sdinv[s] * dn));
        }
    }
}

// ---- A[dst,h]=Σnrm*gw[src,h], B[dst,h]=Σnrm*gb[src,h] (bp-independent) ---
__global__ void k_ab(const float* __restrict__ gw, const float* __restrict__ gb) {
    int w = threadIdx.x >> 5, l = threadIdx.x & 31;
    int n = blockIdx.x * 8 + w;
    int beg = g_rowptr[n], end = g_rowptr[n+1];
    float A0 = 0.f, A1 = 0.f, B0 = 0.f, B1 = 0.f;
    for (int i = beg; i < end; i++) {
        uint2 sn = g_sn[i];
        int s = (int)sn.x;
        float nrm = __uint_as_float(sn.y);
        float2 w2 = *(const float2*)(gw + s*HH + 2*l);
        float2 b2 = *(const float2*)(gb + s*HH + 2*l);
        A0 = fmaf(nrm, w2.x, A0); A1 = fmaf(nrm, w2.y, A1);
        B0 = fmaf(nrm, b2.x, B0); B1 = fmaf(nrm, b2.y, B1);
    }
    __half2 hA = __floats2half2_rn(A0, A1);
    __half2 hB = __floats2half2_rn(B0, B1);
    g_AB[n*32 + l] = make_uint2(*reinterpret_cast<unsigned*>(&hA),
                                *reinterpret_cast<unsigned*>(&hB));
}

// -------- LN1 stats + fp16(x*gw) write in [b][n][p][h] layout -------------
__global__ void k_stats1(const float4* __restrict__ x4,
                         const float4* __restrict__ gw4) {
    int bp = blockIdx.y, ch = blockIdx.x, t = threadIdx.x;
    int b = bp / PP, p = bp - b*PP;
    float s = 0.f, q = 0.f;
    uint2* xg2 = (uint2*)g_xgh;
    #pragma unroll
    for (int i = 0; i < 32; i++) {
        int loc = ch*8192 + i*256 + t;            // float4 index within slice
        float4 v = x4[bp*(NH/4) + loc];
        s += v.x + v.y + v.z + v.w;
        q += v.x*v.x + v.y*v.y + v.z*v.z + v.w*v.w;
        float4 g = gw4[loc];
        __half2 h0 = __floats2half2_rn(v.x*g.x, v.y*g.y);
        __half2 h1 = __floats2half2_rn(v.z*g.z, v.w*g.w);
        int n  = loc >> 4;                        // node
        int h4 = loc & 15;                        // 4-half group within row
        xg2[((b*NN + n)*PP + p)*16 + h4] =
            make_uint2(*reinterpret_cast<unsigned*>(&h0),
                       *reinterpret_cast<unsigned*>(&h1));
    }
    __shared__ float ss[256], sq[256];
    ss[t] = s; sq[t] = q; __syncthreads();
    for (int off = 128; off > 0; off >>= 1) {
        if (t < off) { ss[t] += ss[t+off]; sq[t] += sq[t+off]; }
        __syncthreads();
    }
    if (t == 0) g_part1[bp*4 + ch] = make_float2(ss[0], sq[0]);
}

// -- fused gather: warp = (b, node); contiguous 1536B row per edge ---------
__device__ __forceinline__ void upd(unsigned u, float nrm, float2& a) {
    float2 f = __half22float2(*reinterpret_cast<__half2*>(&u));
    a.x = fmaf(nrm, f.x, a.x);
    a.y = fmaf(nrm, f.y, a.y);
}

__global__ void __launch_bounds__(256) k_conv() {
    __shared__ float2 sstats[PP];
    __shared__ float  ssum[PP][8], ssq[PP][8];
    int b = blockIdx.y;
    int t = threadIdx.x;
    if (t < PP) {                               // inline LN1 finalize
        int bp = b*PP + t;
        float s = 0.f, q = 0.f;
        for (int i = 0; i < 4; i++) { float2 v = g_part1[bp*4+i]; s += v.x; q += v.y; }
        float mean = s / (float)NH;
        float var  = q / (float)NH - mean*mean;
        sstats[t] = make_float2(mean, rsqrtf(var + EPSV));
    }
    __syncthreads();

    int w = t >> 5, l = t & 31;
    int n = blockIdx.x * 8 + w;
    int beg = g_rowptr[n], end = g_rowptr[n+1];
    const uint4* xgb = (const uint4*)g_xgh + (size_t)b * NN * 96;  // 96 uint4/row

    float2 acc[12];
    #pragma unroll
    for (int j = 0; j < 12; j++) acc[j] = make_float2(0.f, 0.f);

    for (int c = beg; c < end; c += 32) {
        int cnt = min(32, end - c);
        uint2 mysn = make_uint2(0u, 0u);
        if (c + l < end) mysn = g_sn[c + l];
        // prefetch edge 0 of this chunk
        unsigned src0 = __shfl_sync(0xffffffffu, mysn.x, 0);
        const uint4* row = xgb + (size_t)src0 * 96;
        uint4 v0 = row[l], v1 = row[32 + l], v2 = row[64 + l];
        for (int j = 0; j < cnt; j++) {
            float nrm = __uint_as_float(__shfl_sync(0xffffffffu, mysn.y, j));
            uint4 c0 = v0, c1 = v1, c2 = v2;
            if (j + 1 < cnt) {                   // 1-deep data prefetch
                unsigned s2 = __shfl_sync(0xffffffffu, mysn.x, j + 1);
                const uint4* r2 = xgb + (size_t)s2 * 96;
                v0 = r2[l]; v1 = r2[32 + l]; v2 = r2[64 + l];
            }
            upd(c0.x, nrm, acc[0]);  upd(c0.y, nrm, acc[1]);
            upd(c0.z, nrm, acc[2]);  upd(c0.w, nrm, acc[3]);
            upd(c1.x, nrm, acc[4]);  upd(c1.y, nrm, acc[5]);
            upd(c1.z, nrm, acc[6]);  upd(c1.w, nrm, acc[7]);
            upd(c2.x, nrm, acc[8]);  upd(c2.y, nrm, acc[9]);
            upd(c2.z, nrm, acc[10]); upd(c2.w, nrm, acc[11]);
        }
    }

    // lane l owns p = 4k + (l>>3) (k=0..2), h = 8*(l&7)..+7
    int g8 = l & 7, pg = l >> 3;
    uint2 ab[4];
    #pragma unroll
    for (int m = 0; m < 4; m++) ab[m] = g_AB[n*32 + 4*g8 + m];

    #pragma unroll
    for (int k = 0; k < 3; k++) {
        int p = 4*k + pg;
        float2 st = sstats[p];
        float r = st.y, mr = st.x * st.y;
        unsigned hy[4];
        float s1 = 0.f, q1 = 0.f;
        #pragma unroll
        for (int m = 0; m < 4; m++) {
            float2 A  = __half22float2(*reinterpret_cast<__half2*>(&ab[m].x));
            float2 Bv = __half22float2(*reinterpret_cast<__half2*>(&ab[m].y));
            float2 a = acc[k*4 + m];
            float y0 = fmaf(r, a.x, fmaf(-mr, A.x, Bv.x));
            float y1 = fmaf(r, a.y, fmaf(-mr, A.y, Bv.y));
            __half2 h = __floats2half2_rn(y0, y1);
            hy[m] = *reinterpret_cast<unsigned*>(&h);
            s1 += y0 + y1;
            q1 += y0*y0 + y1*y1;
        }
        ((uint4*)g_yh)[(size_t)(b*PP + p)*(NH/8) + n*8 + g8] =
            make_uint4(hy[0], hy[1], hy[2], hy[3]);
        // deterministic butterfly over the 8 lanes sharing this p
        #pragma unroll
        for (int off = 1; off < 8; off <<= 1) {
            s1 += __shfl_xor_sync(0xffffffffu, s1, off);
            q1 += __shfl_xor_sync(0xffffffffu, q1, off);
        }
        if (g8 == 0) { ssum[p][w] = s1; ssq[p][w] = q1; }
    }
    __syncthreads();
    if (t < PP) {
        float s = 0.f, q = 0.f;
        for (int i = 0; i < 8; i++) { s += ssum[t][i]; q += ssq[t][i]; }
        g_part2[(b*PP + t)*256 + blockIdx.x] = make_float2(s, q);
    }
}

__global__ void k_stats2() {
    int bp = blockIdx.x, t = threadIdx.x;
    float2 v = g_part2[bp*256 + t];
    __shared__ float ss[256], sq[256];
    ss[t] = v.x; sq[t] = v.y; __syncthreads();
    for (int off = 128; off > 0; off >>= 1) {
        if (t < off) { ss[t] += ss[t+off]; sq[t] += sq[t+off]; }
        __syncthreads();
    }
    if (t == 0) {
        float mean = ss[0] / (float)NH;
        float var  = sq[0] / (float)NH - mean*mean;
        g_stats2[bp] = make_float2(mean, rsqrtf(var + EPSV));
    }
}

// -------- fused LN2 + 1x1 conv over periods + bias (float4 vectorized) ----
__global__ void k_out(const float4* __restrict__ tw4,
                      const float4* __restrict__ tb4,
                      const float*  __restrict__ cw,
                      const float*  __restrict__ cb,
                      float4* __restrict__ out4) {
    __shared__ float  scw[144], srow[12], scb[12];
    __shared__ float2 sst[12];
    int t   = threadIdx.x;
    int gid = blockIdx.x * 256 + t;         // 524288 total (16 b * 2048 n * 16 h4)
    int b   = gid >> 15;                    // 32768 positions per batch
    if (t < 144)             scw[t]       = cw[t];
    if (t >= 144 && t < 156) scb[t-144]   = cb[t-144];
    if (t >= 160 && t < 172) sst[t-160]   = g_stats2[b*PP + (t-160)];
    __syncthreads();
    if (t < 12) {
        float s = 0.f;
        for (int p = 0; p < 12; p++) s += scw[t*12 + p];
        srow[t] = s;
    }
    __syncthreads();

    int h4   = gid & 15;
    int n    = (gid >> 4) & 2047;
    int pos4 = n*16 + h4;

    const uint2* y4 = (const uint2*)g_yh;
    float4 tv[12];
    #pragma unroll
    for (int p = 0; p < 12; p++) {
        uint2 u = y4[(b*PP + p)*(NH/4) + pos4];
        float2 f0 = __half22float2(*reinterpret_cast<__half2*>(&u.x));
        float2 f1 = __half22float2(*reinterpret_cast<__half2*>(&u.y));
        float2 st = sst[p];
        tv[p].x = (f0.x - st.x) * st.y;
        tv[p].y = (f0.y - st.x) * st.y;
        tv[p].z = (f1.x - st.x) * st.y;
        tv[p].w = (f1.y - st.x) * st.y;
    }
    float4 tw = tw4[pos4];
    float4 tb = tb4[pos4];

    #pragma unroll
    for (int q = 0; q < 12; q++) {
        float ax = 0.f, ay = 0.f, az = 0.f, aw = 0.f;
        #pragma unroll
        for (int p = 0; p < 12; p++) {
            float c = scw[q*12 + p];
            ax = fmaf(c, tv[p].x, ax);
            ay = fmaf(c, tv[p].y, ay);
            az = fmaf(c, tv[p].z, az);
            aw = fmaf(c, tv[p].w, aw);
        }
        float4 o;
        o.x = fmaf(tw.x, ax, fmaf(tb.x, srow[q], scb[q]));
        o.y = fmaf(tw.y, ay, fmaf(tb.y, srow[q], scb[q]));
        o.z = fmaf(tw.z, az, fmaf(tb.z, srow[q], scb[q]));
        o.w = fmaf(tw.w, aw, fmaf(tb.w, srow[q], scb[q]));
        out4[(b*PP + q)*(NH/4) + pos4] = o;
    }
}

// --------------------------------------------------------------------------
extern "C" void kernel_launch(void* const* d_in, const int* in_sizes, int n_in,
                              void* d_out, int out_size) {
    const float* x  = (const float*)d_in[0];
    const void*  ei = d_in[1];
    const float* gw = (const float*)d_in[2];
    const float* gb = (const float*)d_in[3];
    const float* tw = (const float*)d_in[4];
    const float* tb = (const float*)d_in[5];
    const float* cw = (const float*)d_in[6];
    const float* cb = (const float*)d_in[7];
    float4* out = (float4*)d_out;

    cudaFuncSetAttribute(k_csr, cudaFuncAttributeMaxDynamicSharedMemorySize, SMEM_CSR);

    k_csr    <<<1, 1024, SMEM_CSR>>>(ei);
    k_ab     <<<256, 256>>>(gw, gb);
    k_stats1 <<<dim3(4, BPc), 256>>>((const float4*)x, (const float4*)gw);
    k_conv   <<<dim3(NN/8, BB), 256>>>();
    k_stats2 <<<BPc, 256>>>();
    k_out    <<<2048, 256>>>((const float4*)tw, (const float4*)tb, cw, cb, out);
}